// round 8
// baseline (speedup 1.0000x reference)
#include <cuda_runtime.h>
#include <math.h>

#define Nn 50000
#define Ee 800000
#define Cc 100000
#define D 128
#define NEG 0.01f
#define BN_EPS 1e-5f
#define NB_SCAN 49

#define FMA2(d, a, b) asm("fma.rn.f32x2 %0, %1, %2, %0;" : "+l"(d) : "l"(a), "l"(b))
#define UNPACK2(lo, hi, v) asm("mov.b64 {%0, %1}, %2;" : "=f"(lo), "=f"(hi) : "l"(v))

// ---------------- scratch (static __device__, no allocation) ----------------
__device__ float g_h0[(size_t)Nn * D];
__device__ float g_h1[(size_t)Nn * D];
__device__ float g_pu[(size_t)Nn * 64];
__device__ float g_pv[(size_t)Nn * 64];
__device__ int   g_deg[Nn];
__device__ int   g_off[Nn + 1];
__device__ int   g_cur[Nn];
__device__ int   g_csr[Ee];
__device__ unsigned long long g_lb[NB_SCAN];  // lookback: (aggregate<<1)|1
__device__ unsigned int g_done;
__device__ float g_part[256];

// ---------------- zero state ----------------
__global__ void k_zero() {
    int i = blockIdx.x * blockDim.x + threadIdx.x;
    if (i < Nn) g_deg[i] = 0;
    if (i < NB_SCAN) g_lb[i] = 0ull;
    if (i == 0) g_done = 0u;
}

__global__ void k_count(const int* __restrict__ dst, int E) {
    for (int e = blockIdx.x * blockDim.x + threadIdx.x; e < E; e += gridDim.x * blockDim.x)
        atomicAdd(&g_deg[dst[e]], 1);
}

// ---------------- single-pass: scan (lookback) + grid barrier + CSR fill ----------------
__global__ void k_scanfill(const int* __restrict__ src, const int* __restrict__ dst, int E) {
    __shared__ int ws[32];
    __shared__ int preds[64];
    __shared__ int sbase;
    int b = blockIdx.x;
    int tid = threadIdx.x;
    int i = b * 1024 + tid;
    int lane = tid & 31, wid = tid >> 5;
    int v = (i < Nn) ? g_deg[i] : 0;
    int s = v;
#pragma unroll
    for (int o = 1; o < 32; o <<= 1) {
        int t = __shfl_up_sync(0xffffffffu, s, o);
        if (lane >= o) s += t;
    }
    if (lane == 31) ws[wid] = s;
    __syncthreads();
    if (wid == 0) {
        int t = ws[lane];
#pragma unroll
        for (int o = 1; o < 32; o <<= 1) {
            int u = __shfl_up_sync(0xffffffffu, t, o);
            if (lane >= o) t += u;
        }
        ws[lane] = t;
    }
    __syncthreads();
    s += wid ? ws[wid - 1] : 0;  // local inclusive

    if (tid == 1023)
        atomicExch(&g_lb[b], (((unsigned long long)(unsigned)s) << 1) | 1ull);

    if (tid < b) {
        unsigned long long x;
        do { x = atomicAdd(&g_lb[tid], 0ull); } while (!(x & 1ull));
        preds[tid] = (int)(x >> 1);
    }
    __syncthreads();
    if (tid == 0) {
        int acc = 0;
        for (int j = 0; j < b; j++) acc += preds[j];
        sbase = acc;
    }
    __syncthreads();
    s += sbase;

    if (i < Nn) {
        g_off[i + 1] = s;
        g_cur[i] = s - v;
    }
    if (i == 0) g_off[0] = 0;

    __threadfence();
    __syncthreads();
    if (tid == 0) {
        atomicAdd(&g_done, 1u);
        while (atomicAdd(&g_done, 0u) < (unsigned)gridDim.x) {}
    }
    __syncthreads();

    int stride = gridDim.x * 1024;
    for (int e = b * 1024 + tid; e < E; e += stride) {
        int d = dst[e];
        int p = atomicAdd(&g_cur[d], 1);
        g_csr[p] = src[e];
    }
}

// ---------------- fused: segment-mean agg + dual GEMM + BN + leaky ----------------
// 32 nodes/block, 512 threads (16 warps x 2 nodes). f32x2 packed FMAs.
// smem: sWs[16384], sWn[16384], sVal[32 nodes x 128 k x 4 (x,x,a,a)] = 16384  -> 192KB
__global__ void k_fused(const float* __restrict__ A,
                        const float* __restrict__ Ws, const float* __restrict__ Wn,
                        const float* __restrict__ bias, const float* __restrict__ gamma,
                        const float* __restrict__ beta, const float* __restrict__ rm,
                        const float* __restrict__ rv, float* __restrict__ out, int fixnan) {
    extern __shared__ float sm[];
    float* sWs = sm;                // [0, 16384)
    float* sWn = sm + 16384;        // [16384, 32768)
    float* sVal = sm + 32768;       // [32768, 49152)  node stride 512 floats
    {
        float4* d0 = (float4*)sWs; const float4* s0 = (const float4*)Ws;
        float4* d1 = (float4*)sWn; const float4* s1 = (const float4*)Wn;
        for (int i = threadIdx.x; i < 4096; i += 512) { d0[i] = s0[i]; d1[i] = s1[i]; }
    }
    __syncthreads();

    int w = threadIdx.x >> 5, l = threadIdx.x & 31;
    int nl0 = w * 2;
    int n0 = blockIdx.x * 32 + nl0;

    // phase A: gather-mean + self row, stored (x,x,a,a) per k
#pragma unroll
    for (int t = 0; t < 2; t++) {
        int node = n0 + t;
        float4 xv = make_float4(0.f, 0.f, 0.f, 0.f);
        float4 ag = make_float4(0.f, 0.f, 0.f, 0.f);
        if (node < Nn) {
            xv = ((const float4*)(A + (size_t)node * D))[l];
            int s = g_off[node], e = g_off[node + 1];
            float4 a1 = make_float4(0.f, 0.f, 0.f, 0.f);
            float4 a2 = make_float4(0.f, 0.f, 0.f, 0.f);
            float4 a3 = make_float4(0.f, 0.f, 0.f, 0.f);
            int i = s;
            for (; i + 4 <= e; i += 4) {
                int s0 = g_csr[i], s1 = g_csr[i + 1], s2 = g_csr[i + 2], s3 = g_csr[i + 3];
                float4 v0 = ((const float4*)(A + (size_t)s0 * D))[l];
                float4 v1 = ((const float4*)(A + (size_t)s1 * D))[l];
                float4 v2 = ((const float4*)(A + (size_t)s2 * D))[l];
                float4 v3 = ((const float4*)(A + (size_t)s3 * D))[l];
                ag.x += v0.x; ag.y += v0.y; ag.z += v0.z; ag.w += v0.w;
                a1.x += v1.x; a1.y += v1.y; a1.z += v1.z; a1.w += v1.w;
                a2.x += v2.x; a2.y += v2.y; a2.z += v2.z; a2.w += v2.w;
                a3.x += v3.x; a3.y += v3.y; a3.z += v3.z; a3.w += v3.w;
            }
            for (; i < e; i++) {
                int sr = g_csr[i];
                float4 vv = ((const float4*)(A + (size_t)sr * D))[l];
                ag.x += vv.x; ag.y += vv.y; ag.z += vv.z; ag.w += vv.w;
            }
            ag.x += a1.x + a2.x + a3.x;
            ag.y += a1.y + a2.y + a3.y;
            ag.z += a1.z + a2.z + a3.z;
            ag.w += a1.w + a2.w + a3.w;
            int deg = e - s;
            float inv = 1.0f / (float)(deg > 1 ? deg : 1);
            ag.x *= inv; ag.y *= inv; ag.z *= inv; ag.w *= inv;
        }
        float4* sd = (float4*)(sVal + (nl0 + t) * 512 + l * 16);
        sd[0] = make_float4(xv.x, xv.x, ag.x, ag.x);
        sd[1] = make_float4(xv.y, xv.y, ag.y, ag.y);
        sd[2] = make_float4(xv.z, xv.z, ag.z, ag.z);
        sd[3] = make_float4(xv.w, xv.w, ag.w, ag.w);
    }
    __syncwarp();

    // phase B: h = x@Ws + agg@Wn using f32x2; thread: 2 nodes x 4 cols
    int c = l * 4;
    const float* wsb = sWs + c;
    const float* wnb = sWn + c;
    const float* vb = sVal + nl0 * 512;
    unsigned long long a01[2] = {0ull, 0ull};
    unsigned long long a23[2] = {0ull, 0ull};
#pragma unroll 8
    for (int k = 0; k < 128; k++) {
        ulonglong2 wsp = *(const ulonglong2*)(wsb + k * 128);
        ulonglong2 wnp = *(const ulonglong2*)(wnb + k * 128);
#pragma unroll
        for (int t = 0; t < 2; t++) {
            ulonglong2 va = *(const ulonglong2*)(vb + t * 512 + k * 4);  // (x,x),(a,a)
            FMA2(a01[t], va.x, wsp.x);
            FMA2(a23[t], va.x, wsp.y);
            FMA2(a01[t], va.y, wnp.x);
            FMA2(a23[t], va.y, wnp.y);
        }
    }

    // epilogue
    float4 bb = *(const float4*)&bias[c];
    float4 ga = *(const float4*)&gamma[c];
    float4 be = *(const float4*)&beta[c];
    float4 rmv = *(const float4*)&rm[c];
    float4 rvv = *(const float4*)&rv[c];
    float sc[4], sh[4];
    sc[0] = ga.x * rsqrtf(rvv.x + BN_EPS); sh[0] = be.x - rmv.x * sc[0];
    sc[1] = ga.y * rsqrtf(rvv.y + BN_EPS); sh[1] = be.y - rmv.y * sc[1];
    sc[2] = ga.z * rsqrtf(rvv.z + BN_EPS); sh[2] = be.z - rmv.z * sc[2];
    sc[3] = ga.w * rsqrtf(rvv.w + BN_EPS); sh[3] = be.w - rmv.w * sc[3];
    const float* bbp = (const float*)&bb;
#pragma unroll
    for (int t = 0; t < 2; t++) {
        int node = n0 + t;
        if (node >= Nn) continue;
        float o[4];
        UNPACK2(o[0], o[1], a01[t]);
        UNPACK2(o[2], o[3], a23[t]);
#pragma unroll
        for (int j = 0; j < 4; j++) {
            float vv = o[j] + bbp[j];
            vv = vv * sc[j] + sh[j];
            vv = vv >= 0.f ? vv : NEG * vv;
            if (fixnan) {
                if (isnan(vv)) vv = 1e-14f;
                else if (isinf(vv)) vv = vv > 0.f ? 3.402823466e38f : -3.402823466e38f;
            }
            o[j] = vv;
        }
        *(float4*)&out[(size_t)node * D + c] = make_float4(o[0], o[1], o[2], o[3]);
    }
}

// ---------------- node-level MLP layer0 projection (f32x2) ----------------
// 64 nodes/block, 512 threads (16 warps x 4 nodes); lane l -> cols (2l, 2l+1).
// smem: sWI[16384] interleaved (wu0,wu1,wv0,wv1), sVal[64 nodes x 256 dup] = 16384. 128KB
__global__ void k_prep(const float* __restrict__ h, const float* __restrict__ mw0,
                       float* __restrict__ pu, float* __restrict__ pv) {
    extern __shared__ float sm[];
    float* sWI = sm;            // [0, 16384)
    float* sVal = sm + 16384;   // [16384, 32768)  node stride 256
    for (int idx = threadIdx.x; idx < 4096; idx += 512) {
        int k = idx >> 5, p = idx & 31;
        float2 u = *(const float2*)&mw0[k * 64 + 2 * p];
        float2 v = *(const float2*)&mw0[(128 + k) * 64 + 2 * p];
        *(float4*)&sWI[k * 128 + p * 4] = make_float4(u.x, u.y, v.x, v.y);
    }
    __syncthreads();

    int w = threadIdx.x >> 5, l = threadIdx.x & 31;
    int nl0 = w * 4;
    int n0 = blockIdx.x * 64 + nl0;

#pragma unroll
    for (int t = 0; t < 4; t++) {
        int node = n0 + t;
        float4 xv = make_float4(0.f, 0.f, 0.f, 0.f);
        if (node < Nn) xv = ((const float4*)(h + (size_t)node * D))[l];
        float4* sd = (float4*)(sVal + (nl0 + t) * 256 + l * 8);
        sd[0] = make_float4(xv.x, xv.x, xv.y, xv.y);
        sd[1] = make_float4(xv.z, xv.z, xv.w, xv.w);
    }
    __syncwarp();

    unsigned long long au[4] = {0ull, 0ull, 0ull, 0ull};
    unsigned long long av[4] = {0ull, 0ull, 0ull, 0ull};
    const float* wib = sWI + l * 4;
    const float* vb = sVal + nl0 * 256;
#pragma unroll 8
    for (int k = 0; k < 128; k++) {
        ulonglong2 wp = *(const ulonglong2*)(wib + k * 128);  // (wu pair, wv pair)
#pragma unroll
        for (int t = 0; t < 4; t++) {
            unsigned long long xd = *(const unsigned long long*)(vb + t * 256 + 2 * k);
            FMA2(au[t], xd, wp.x);
            FMA2(av[t], xd, wp.y);
        }
    }
#pragma unroll
    for (int t = 0; t < 4; t++) {
        int node = n0 + t;
        if (node >= Nn) continue;
        *(float2*)&pu[(size_t)node * 64 + 2 * l] = *(float2*)&au[t];
        *(float2*)&pv[(size_t)node * 64 + 2 * l] = *(float2*)&av[t];
    }
}

// ---------------- candidate kernel ----------------
#define Z0STRIDE 136
#define CAND_SMEM_FLOATS 13060
__global__ void k_cand(const float* __restrict__ pu, const float* __restrict__ pv,
                       const int* __restrict__ cu, const int* __restrict__ cv,
                       const float* __restrict__ cf,
                       const float* __restrict__ mw0, const float* __restrict__ mb0,
                       const float* __restrict__ mw1, const float* __restrict__ mb1,
                       const float* __restrict__ mw2, const float* __restrict__ mb2,
                       float* __restrict__ y, int C) {
    extern __shared__ float smc[];
    float* w1s = smc;
    float* z0sD = smc + 4096;
    float* wfs = smc + 12800;
    float* b0s = smc + 12864;
    float* b1s = smc + 12928;
    float* w2s = smc + 12992;
    float* b2s = smc + 13056;
    int tid = threadIdx.x;
    for (int i = tid; i < 4096; i += 256) w1s[i] = mw1[i];
    if (tid < 64) {
        wfs[tid] = mw0[256 * 64 + tid];
        b0s[tid] = mb0[tid];
        b1s[tid] = mb1[tid];
        w2s[tid] = mw2[tid];
    }
    if (tid == 0) b2s[0] = mb2[0];
    __syncthreads();

    int base = blockIdx.x * 64;

    {
        int jc = tid & 15, j = jc * 4;
        int c0 = tid >> 4;
#pragma unroll
        for (int i = 0; i < 4; i++) {
            int cl = c0 + 16 * i;
            int gc = base + cl;
            float4 z = make_float4(0.f, 0.f, 0.f, 0.f);
            if (gc < C) {
                int u = cu[gc], v = cv[gc];
                float f = cf[gc];
                float4 a = *(const float4*)&pu[(size_t)u * 64 + j];
                float4 b = *(const float4*)&pv[(size_t)v * 64 + j];
                float4 wf4 = *(const float4*)&wfs[j];
                float4 bb4 = *(const float4*)&b0s[j];
                z.x = a.x + b.x + f * wf4.x + bb4.x;
                z.y = a.y + b.y + f * wf4.y + bb4.y;
                z.z = a.z + b.z + f * wf4.z + bb4.z;
                z.w = a.w + b.w + f * wf4.w + bb4.w;
                z.x = z.x >= 0.f ? z.x : NEG * z.x;
                z.y = z.y >= 0.f ? z.y : NEG * z.y;
                z.z = z.z >= 0.f ? z.z : NEG * z.z;
                z.w = z.w >= 0.f ? z.w : NEG * z.w;
            }
            float* zd = &z0sD[cl * Z0STRIDE + 2 * j];
            ((float4*)zd)[0] = make_float4(z.x, z.x, z.y, z.y);
            ((float4*)zd)[1] = make_float4(z.z, z.z, z.w, z.w);
        }
    }
    __syncthreads();

    {
        int oc = tid & 15, cg = tid >> 4;
        int ob = oc * 4;
        unsigned long long a01[4] = {0ull, 0ull, 0ull, 0ull};
        unsigned long long a23[4] = {0ull, 0ull, 0ull, 0ull};
        const float* z0 = &z0sD[(cg * 4 + 0) * Z0STRIDE];
        const float* z1 = &z0sD[(cg * 4 + 1) * Z0STRIDE];
        const float* z2 = &z0sD[(cg * 4 + 2) * Z0STRIDE];
        const float* z3 = &z0sD[(cg * 4 + 3) * Z0STRIDE];
#pragma unroll 8
        for (int k = 0; k < 64; k++) {
            ulonglong2 wp = *(const ulonglong2*)&w1s[k * 64 + ob];
            unsigned long long q0 = *(const unsigned long long*)(z0 + 2 * k);
            unsigned long long q1 = *(const unsigned long long*)(z1 + 2 * k);
            unsigned long long q2 = *(const unsigned long long*)(z2 + 2 * k);
            unsigned long long q3 = *(const unsigned long long*)(z3 + 2 * k);
            FMA2(a01[0], q0, wp.x); FMA2(a23[0], q0, wp.y);
            FMA2(a01[1], q1, wp.x); FMA2(a23[1], q1, wp.y);
            FMA2(a01[2], q2, wp.x); FMA2(a23[2], q2, wp.y);
            FMA2(a01[3], q3, wp.x); FMA2(a23[3], q3, wp.y);
        }
        float4 bb = *(const float4*)&b1s[ob];
        float4 w2v = *(const float4*)&w2s[ob];
        float part[4];
#pragma unroll
        for (int q = 0; q < 4; q++) {
            float t0, t1, t2, t3;
            UNPACK2(t0, t1, a01[q]);
            UNPACK2(t2, t3, a23[q]);
            t0 += bb.x; t0 = t0 >= 0.f ? t0 : NEG * t0;
            t1 += bb.y; t1 = t1 >= 0.f ? t1 : NEG * t1;
            t2 += bb.z; t2 = t2 >= 0.f ? t2 : NEG * t2;
            t3 += bb.w; t3 = t3 >= 0.f ? t3 : NEG * t3;
            part[q] = t0 * w2v.x + t1 * w2v.y + t2 * w2v.z + t3 * w2v.w;
        }
#pragma unroll
        for (int q = 0; q < 4; q++) {
#pragma unroll
            for (int o = 8; o; o >>= 1)
                part[q] += __shfl_xor_sync(0xffffffffu, part[q], o);
        }
        if (oc == 0) {
#pragma unroll
            for (int q = 0; q < 4; q++) {
                int gc = base + cg * 4 + q;
                if (gc < C) y[gc] = part[q] + b2s[0];
            }
        }
    }
}

// ---------------- softmax (2 kernels, deterministic) ----------------
__global__ void k_softA(const float* __restrict__ y, int C) {
    __shared__ float mm[256], ss[256];
    float m = -3.402823466e38f, s = 0.f;
    for (int i = blockIdx.x * 256 + threadIdx.x; i < C; i += gridDim.x * 256) {
        float v = y[i];
        if (v > m) { s = s * expf(m - v) + 1.0f; m = v; }
        else s += expf(v - m);
    }
    mm[threadIdx.x] = m; ss[threadIdx.x] = s;
    __syncthreads();
    for (int st = 128; st; st >>= 1) {
        if (threadIdx.x < st) {
            float m2 = mm[threadIdx.x + st], s2 = ss[threadIdx.x + st];
            float M = fmaxf(mm[threadIdx.x], m2);
            ss[threadIdx.x] = ss[threadIdx.x] * expf(mm[threadIdx.x] - M) + s2 * expf(m2 - M);
            mm[threadIdx.x] = M;
        }
        __syncthreads();
    }
    if (threadIdx.x == 0) { g_part[blockIdx.x] = mm[0]; g_part[128 + blockIdx.x] = ss[0]; }
}

__global__ void k_softFin(const float* __restrict__ y, float* __restrict__ out, int C) {
    __shared__ float mm[128], ss[128];
    int t = threadIdx.x;
    if (t < 128) { mm[t] = g_part[t]; ss[t] = g_part[128 + t]; }
    __syncthreads();
    for (int st = 64; st; st >>= 1) {
        if (t < st) {
            float m2 = mm[t + st], s2 = ss[t + st];
            float M = fmaxf(mm[t], m2);
            ss[t] = ss[t] * expf(mm[t] - M) + s2 * expf(m2 - M);
            mm[t] = M;
        }
        __syncthreads();
    }
    float mx = mm[0];
    float inv = 1.0f / ss[0];
    for (int i = blockIdx.x * 256 + t; i < C; i += gridDim.x * 256)
        out[i] = expf(y[i] - mx) * inv;
}

// ---------------- host launcher ----------------
extern "C" void kernel_launch(void* const* d_in, const int* in_sizes, int n_in,
                              void* d_out, int out_size) {
    const float* x   = (const float*)d_in[0];
    const int* src   = (const int*)d_in[1];
    const int* dst   = (const int*)d_in[2];
    const int* cu    = (const int*)d_in[3];
    const int* cv    = (const int*)d_in[4];
    const float* cf  = (const float*)d_in[5];
    const float* ws0 = (const float*)d_in[6];
    const float* wn0 = (const float*)d_in[7];
    const float* b0  = (const float*)d_in[8];
    const float* ga0 = (const float*)d_in[9];
    const float* be0 = (const float*)d_in[10];
    const float* rm0 = (const float*)d_in[11];
    const float* rv0 = (const float*)d_in[12];
    const float* ws1 = (const float*)d_in[13];
    const float* wn1 = (const float*)d_in[14];
    const float* b1  = (const float*)d_in[15];
    const float* ga1 = (const float*)d_in[16];
    const float* be1 = (const float*)d_in[17];
    const float* rm1 = (const float*)d_in[18];
    const float* rv1 = (const float*)d_in[19];
    const float* mw0 = (const float*)d_in[20];
    const float* mb0 = (const float*)d_in[21];
    const float* mw1 = (const float*)d_in[22];
    const float* mb1 = (const float*)d_in[23];
    const float* mw2 = (const float*)d_in[24];
    const float* mb2 = (const float*)d_in[25];

    int E = in_sizes[1];
    int C = in_sizes[3];
    float* y = (float*)d_out;
    float* soft = y + C;

    float *h0p, *h1p, *pup, *pvp;
    cudaGetSymbolAddress((void**)&h0p, g_h0);
    cudaGetSymbolAddress((void**)&h1p, g_h1);
    cudaGetSymbolAddress((void**)&pup, g_pu);
    cudaGetSymbolAddress((void**)&pvp, g_pv);

    cudaFuncSetAttribute(k_fused, cudaFuncAttributeMaxDynamicSharedMemorySize, 196608);
    cudaFuncSetAttribute(k_prep, cudaFuncAttributeMaxDynamicSharedMemorySize, 131072);
    cudaFuncSetAttribute(k_cand, cudaFuncAttributeMaxDynamicSharedMemorySize, CAND_SMEM_FLOATS * 4);

    // 1: zero state
    k_zero<<<(Nn + 255) / 256, 256>>>();
    // 2: degree count
    k_count<<<1024, 256>>>(dst, E);
    // 3: scan + fill (single pass)
    k_scanfill<<<NB_SCAN, 1024>>>(src, dst, E);
    // 4: layer 0 (profiled position)
    k_fused<<<(Nn + 31) / 32, 512, 196608>>>(x, ws0, wn0, b0, ga0, be0, rm0, rv0, h0p, 0);
    // 5: layer 1 (+ nan_to_num)
    k_fused<<<(Nn + 31) / 32, 512, 196608>>>(h0p, ws1, wn1, b1, ga1, be1, rm1, rv1, h1p, 1);
    // 6: MLP layer0 hoisted to node level
    k_prep<<<(Nn + 63) / 64, 512, 131072>>>(h1p, mw0, pup, pvp);
    // 7: candidate tail -> y
    k_cand<<<(C + 63) / 64, 256, CAND_SMEM_FLOATS * 4>>>(pup, pvp, cu, cv, cf, mw0, mb0, mw1, mb1, mw2, mb2, y, C);
    // 8,9: softmax
    k_softA<<<128, 256>>>(y, C);
    k_softFin<<<256, 256>>>(y, soft, C);
}

// round 9
// speedup vs baseline: 1.3980x; 1.3980x over previous
#include <cuda_runtime.h>
#include <math.h>

#define Nn 50000
#define Ee 800000
#define Cc 100000
#define D 128
#define NEG 0.01f
#define BN_EPS 1e-5f
#define NB_SCAN 49

#define FMA2(d, a, b) asm("fma.rn.f32x2 %0, %1, %2, %0;" : "+l"(d) : "l"(a), "l"(b))
#define UNPACK2(lo, hi, v) asm("mov.b64 {%0, %1}, %2;" : "=f"(lo), "=f"(hi) : "l"(v))
#define PACK2DUP(d, v) asm("mov.b64 %0, {%1, %1};" : "=l"(d) : "f"(v))

// ---------------- scratch (static __device__, no allocation) ----------------
__device__ float g_h0[(size_t)Nn * D];
__device__ float g_h1[(size_t)Nn * D];
__device__ float g_pu[(size_t)Nn * 64];
__device__ float g_pv[(size_t)Nn * 64];
__device__ int   g_deg[Nn];
__device__ int   g_off[Nn + 1];
__device__ int   g_cur[Nn];
__device__ int   g_csr[Ee];
__device__ unsigned long long g_lb[NB_SCAN];  // lookback: (aggregate<<1)|1
__device__ unsigned int g_done;
__device__ float g_part[256];

// ---------------- zero state ----------------
__global__ void k_zero() {
    int i = blockIdx.x * blockDim.x + threadIdx.x;
    if (i < Nn) g_deg[i] = 0;
    if (i < NB_SCAN) g_lb[i] = 0ull;
    if (i == 0) g_done = 0u;
}

__global__ void k_count(const int* __restrict__ dst, int E) {
    for (int e = blockIdx.x * blockDim.x + threadIdx.x; e < E; e += gridDim.x * blockDim.x)
        atomicAdd(&g_deg[dst[e]], 1);
}

// ---------------- single-pass: scan (lookback) + grid barrier + CSR fill ----------------
__global__ void k_scanfill(const int* __restrict__ src, const int* __restrict__ dst, int E) {
    __shared__ int ws[32];
    __shared__ int preds[64];
    __shared__ int sbase;
    int b = blockIdx.x;
    int tid = threadIdx.x;
    int i = b * 1024 + tid;
    int lane = tid & 31, wid = tid >> 5;
    int v = (i < Nn) ? g_deg[i] : 0;
    int s = v;
#pragma unroll
    for (int o = 1; o < 32; o <<= 1) {
        int t = __shfl_up_sync(0xffffffffu, s, o);
        if (lane >= o) s += t;
    }
    if (lane == 31) ws[wid] = s;
    __syncthreads();
    if (wid == 0) {
        int t = ws[lane];
#pragma unroll
        for (int o = 1; o < 32; o <<= 1) {
            int u = __shfl_up_sync(0xffffffffu, t, o);
            if (lane >= o) t += u;
        }
        ws[lane] = t;
    }
    __syncthreads();
    s += wid ? ws[wid - 1] : 0;  // local inclusive

    if (tid == 1023)
        atomicExch(&g_lb[b], (((unsigned long long)(unsigned)s) << 1) | 1ull);

    if (tid < b) {
        unsigned long long x;
        do { x = atomicAdd(&g_lb[tid], 0ull); } while (!(x & 1ull));
        preds[tid] = (int)(x >> 1);
    }
    __syncthreads();
    if (tid == 0) {
        int acc = 0;
        for (int j = 0; j < b; j++) acc += preds[j];
        sbase = acc;
    }
    __syncthreads();
    s += sbase;

    if (i < Nn) {
        g_off[i + 1] = s;
        g_cur[i] = s - v;
    }
    if (i == 0) g_off[0] = 0;

    __threadfence();
    __syncthreads();
    if (tid == 0) {
        atomicAdd(&g_done, 1u);
        while (atomicAdd(&g_done, 0u) < (unsigned)gridDim.x) {}
    }
    __syncthreads();

    int stride = gridDim.x * 1024;
    for (int e = b * 1024 + tid; e < E; e += stride) {
        int d = dst[e];
        int p = atomicAdd(&g_cur[d], 1);
        g_csr[p] = src[e];
    }
}

// ---------------- fused: segment-mean agg + dual GEMM + BN + leaky ----------------
// 64 nodes/block, 512 threads (16 warps x 4 nodes). f32x2 packed FMAs.
// smem: sWs[16384], sWn[16384], sVal[64 nodes x 128 k x (x,a)] = 16384  -> 192KB
__global__ void k_fused(const float* __restrict__ A,
                        const float* __restrict__ Ws, const float* __restrict__ Wn,
                        const float* __restrict__ bias, const float* __restrict__ gamma,
                        const float* __restrict__ beta, const float* __restrict__ rm,
                        const float* __restrict__ rv, float* __restrict__ out, int fixnan) {
    extern __shared__ float sm[];
    float* sWs = sm;                // [0, 16384)
    float* sWn = sm + 16384;        // [16384, 32768)
    float* sVal = sm + 32768;       // [32768, 49152)  node stride 256 floats
    {
        float4* d0 = (float4*)sWs; const float4* s0 = (const float4*)Ws;
        float4* d1 = (float4*)sWn; const float4* s1 = (const float4*)Wn;
        for (int i = threadIdx.x; i < 4096; i += 512) { d0[i] = s0[i]; d1[i] = s1[i]; }
    }
    __syncthreads();

    int w = threadIdx.x >> 5, l = threadIdx.x & 31;
    int nl0 = w * 4;
    int n0 = blockIdx.x * 64 + nl0;

    // phase A: gather-mean + self row. Cooperative csr load (one coalesced LDG
    // per 32 edges, indices broadcast via shfl). Stored interleaved (x_k, a_k).
#pragma unroll
    for (int t = 0; t < 4; t++) {
        int node = n0 + t;
        float4 xv = make_float4(0.f, 0.f, 0.f, 0.f);
        float4 ag = make_float4(0.f, 0.f, 0.f, 0.f);
        if (node < Nn) {
            xv = ((const float4*)(A + (size_t)node * D))[l];
            int s = g_off[node], e = g_off[node + 1];
            float4 a1 = make_float4(0.f, 0.f, 0.f, 0.f);
            float4 a2 = make_float4(0.f, 0.f, 0.f, 0.f);
            float4 a3 = make_float4(0.f, 0.f, 0.f, 0.f);
            for (int base = s; base < e; base += 32) {
                int cnt = e - base; if (cnt > 32) cnt = 32;
                int idx = (l < cnt) ? g_csr[base + l] : 0;
                int j = 0;
                for (; j + 4 <= cnt; j += 4) {
                    int r0 = __shfl_sync(0xffffffffu, idx, j);
                    int r1 = __shfl_sync(0xffffffffu, idx, j + 1);
                    int r2 = __shfl_sync(0xffffffffu, idx, j + 2);
                    int r3 = __shfl_sync(0xffffffffu, idx, j + 3);
                    float4 v0 = ((const float4*)(A + (size_t)r0 * D))[l];
                    float4 v1 = ((const float4*)(A + (size_t)r1 * D))[l];
                    float4 v2 = ((const float4*)(A + (size_t)r2 * D))[l];
                    float4 v3 = ((const float4*)(A + (size_t)r3 * D))[l];
                    ag.x += v0.x; ag.y += v0.y; ag.z += v0.z; ag.w += v0.w;
                    a1.x += v1.x; a1.y += v1.y; a1.z += v1.z; a1.w += v1.w;
                    a2.x += v2.x; a2.y += v2.y; a2.z += v2.z; a2.w += v2.w;
                    a3.x += v3.x; a3.y += v3.y; a3.z += v3.z; a3.w += v3.w;
                }
                for (; j < cnt; j++) {
                    int r = __shfl_sync(0xffffffffu, idx, j);
                    float4 vv = ((const float4*)(A + (size_t)r * D))[l];
                    ag.x += vv.x; ag.y += vv.y; ag.z += vv.z; ag.w += vv.w;
                }
            }
            ag.x += a1.x + a2.x + a3.x;
            ag.y += a1.y + a2.y + a3.y;
            ag.z += a1.z + a2.z + a3.z;
            ag.w += a1.w + a2.w + a3.w;
            int deg = e - s;
            float inv = 1.0f / (float)(deg > 1 ? deg : 1);
            ag.x *= inv; ag.y *= inv; ag.z *= inv; ag.w *= inv;
        }
        // dims 4l..4l+3: pairs (x_k, a_k) at sVal[node*256 + 2k]
        float4* sd = (float4*)(sVal + (nl0 + t) * 256 + l * 8);
        sd[0] = make_float4(xv.x, ag.x, xv.y, ag.y);
        sd[1] = make_float4(xv.z, ag.z, xv.w, ag.w);
    }
    __syncwarp();

    // phase B: h = x@Ws + agg@Wn using f32x2; thread: 4 nodes x 4 cols
    int c = l * 4;
    const float* wsb = sWs + c;
    const float* wnb = sWn + c;
    const float* vb = sVal + nl0 * 256;
    unsigned long long a01[4] = {0ull, 0ull, 0ull, 0ull};
    unsigned long long a23[4] = {0ull, 0ull, 0ull, 0ull};
#pragma unroll 4
    for (int k = 0; k < 128; k++) {
        ulonglong2 wsp = *(const ulonglong2*)(wsb + k * 128);
        ulonglong2 wnp = *(const ulonglong2*)(wnb + k * 128);
#pragma unroll
        for (int t = 0; t < 4; t++) {
            float2 xa = *(const float2*)(vb + t * 256 + 2 * k);  // broadcast (x_k, a_k)
            unsigned long long xx, aa;
            PACK2DUP(xx, xa.x);
            PACK2DUP(aa, xa.y);
            FMA2(a01[t], xx, wsp.x);
            FMA2(a23[t], xx, wsp.y);
            FMA2(a01[t], aa, wnp.x);
            FMA2(a23[t], aa, wnp.y);
        }
    }

    // epilogue
    float4 bb = *(const float4*)&bias[c];
    float4 ga = *(const float4*)&gamma[c];
    float4 be = *(const float4*)&beta[c];
    float4 rmv = *(const float4*)&rm[c];
    float4 rvv = *(const float4*)&rv[c];
    float sc[4], sh[4];
    sc[0] = ga.x * rsqrtf(rvv.x + BN_EPS); sh[0] = be.x - rmv.x * sc[0];
    sc[1] = ga.y * rsqrtf(rvv.y + BN_EPS); sh[1] = be.y - rmv.y * sc[1];
    sc[2] = ga.z * rsqrtf(rvv.z + BN_EPS); sh[2] = be.z - rmv.z * sc[2];
    sc[3] = ga.w * rsqrtf(rvv.w + BN_EPS); sh[3] = be.w - rmv.w * sc[3];
    const float* bbp = (const float*)&bb;
#pragma unroll
    for (int t = 0; t < 4; t++) {
        int node = n0 + t;
        if (node >= Nn) continue;
        float o[4];
        UNPACK2(o[0], o[1], a01[t]);
        UNPACK2(o[2], o[3], a23[t]);
#pragma unroll
        for (int j = 0; j < 4; j++) {
            float vv = o[j] + bbp[j];
            vv = vv * sc[j] + sh[j];
            vv = vv >= 0.f ? vv : NEG * vv;
            if (fixnan) {
                if (isnan(vv)) vv = 1e-14f;
                else if (isinf(vv)) vv = vv > 0.f ? 3.402823466e38f : -3.402823466e38f;
            }
            o[j] = vv;
        }
        *(float4*)&out[(size_t)node * D + c] = make_float4(o[0], o[1], o[2], o[3]);
    }
}

// ---------------- node-level MLP layer0 projection (f32x2) ----------------
// 64 nodes/block, 512 threads (16 warps x 4 nodes); lane l -> cols (2l, 2l+1).
__global__ void k_prep(const float* __restrict__ h, const float* __restrict__ mw0,
                       float* __restrict__ pu, float* __restrict__ pv) {
    extern __shared__ float sm[];
    float* sWI = sm;            // [0, 16384)
    float* sVal = sm + 16384;   // [16384, 32768)  node stride 256
    for (int idx = threadIdx.x; idx < 4096; idx += 512) {
        int k = idx >> 5, p = idx & 31;
        float2 u = *(const float2*)&mw0[k * 64 + 2 * p];
        float2 v = *(const float2*)&mw0[(128 + k) * 64 + 2 * p];
        *(float4*)&sWI[k * 128 + p * 4] = make_float4(u.x, u.y, v.x, v.y);
    }
    __syncthreads();

    int w = threadIdx.x >> 5, l = threadIdx.x & 31;
    int nl0 = w * 4;
    int n0 = blockIdx.x * 64 + nl0;

#pragma unroll
    for (int t = 0; t < 4; t++) {
        int node = n0 + t;
        float4 xv = make_float4(0.f, 0.f, 0.f, 0.f);
        if (node < Nn) xv = ((const float4*)(h + (size_t)node * D))[l];
        float4* sd = (float4*)(sVal + (nl0 + t) * 256 + l * 8);
        sd[0] = make_float4(xv.x, xv.x, xv.y, xv.y);
        sd[1] = make_float4(xv.z, xv.z, xv.w, xv.w);
    }
    __syncwarp();

    unsigned long long au[4] = {0ull, 0ull, 0ull, 0ull};
    unsigned long long av[4] = {0ull, 0ull, 0ull, 0ull};
    const float* wib = sWI + l * 4;
    const float* vb = sVal + nl0 * 256;
#pragma unroll 8
    for (int k = 0; k < 128; k++) {
        ulonglong2 wp = *(const ulonglong2*)(wib + k * 128);  // (wu pair, wv pair)
#pragma unroll
        for (int t = 0; t < 4; t++) {
            unsigned long long xd = *(const unsigned long long*)(vb + t * 256 + 2 * k);
            FMA2(au[t], xd, wp.x);
            FMA2(av[t], xd, wp.y);
        }
    }
#pragma unroll
    for (int t = 0; t < 4; t++) {
        int node = n0 + t;
        if (node >= Nn) continue;
        *(float2*)&pu[(size_t)node * 64 + 2 * l] = *(float2*)&au[t];
        *(float2*)&pv[(size_t)node * 64 + 2 * l] = *(float2*)&av[t];
    }
}

// ---------------- candidate kernel ----------------
#define Z0STRIDE 136
#define CAND_SMEM_FLOATS 13060
__global__ void k_cand(const float* __restrict__ pu, const float* __restrict__ pv,
                       const int* __restrict__ cu, const int* __restrict__ cv,
                       const float* __restrict__ cf,
                       const float* __restrict__ mw0, const float* __restrict__ mb0,
                       const float* __restrict__ mw1, const float* __restrict__ mb1,
                       const float* __restrict__ mw2, const float* __restrict__ mb2,
                       float* __restrict__ y, int C) {
    extern __shared__ float smc[];
    float* w1s = smc;
    float* z0sD = smc + 4096;
    float* wfs = smc + 12800;
    float* b0s = smc + 12864;
    float* b1s = smc + 12928;
    float* w2s = smc + 12992;
    float* b2s = smc + 13056;
    int tid = threadIdx.x;
    for (int i = tid; i < 4096; i += 256) w1s[i] = mw1[i];
    if (tid < 64) {
        wfs[tid] = mw0[256 * 64 + tid];
        b0s[tid] = mb0[tid];
        b1s[tid] = mb1[tid];
        w2s[tid] = mw2[tid];
    }
    if (tid == 0) b2s[0] = mb2[0];
    __syncthreads();

    int base = blockIdx.x * 64;

    {
        int jc = tid & 15, j = jc * 4;
        int c0 = tid >> 4;
#pragma unroll
        for (int i = 0; i < 4; i++) {
            int cl = c0 + 16 * i;
            int gc = base + cl;
            float4 z = make_float4(0.f, 0.f, 0.f, 0.f);
            if (gc < C) {
                int u = cu[gc], v = cv[gc];
                float f = cf[gc];
                float4 a = *(const float4*)&pu[(size_t)u * 64 + j];
                float4 b = *(const float4*)&pv[(size_t)v * 64 + j];
                float4 wf4 = *(const float4*)&wfs[j];
                float4 bb4 = *(const float4*)&b0s[j];
                z.x = a.x + b.x + f * wf4.x + bb4.x;
                z.y = a.y + b.y + f * wf4.y + bb4.y;
                z.z = a.z + b.z + f * wf4.z + bb4.z;
                z.w = a.w + b.w + f * wf4.w + bb4.w;
                z.x = z.x >= 0.f ? z.x : NEG * z.x;
                z.y = z.y >= 0.f ? z.y : NEG * z.y;
                z.z = z.z >= 0.f ? z.z : NEG * z.z;
                z.w = z.w >= 0.f ? z.w : NEG * z.w;
            }
            float* zd = &z0sD[cl * Z0STRIDE + 2 * j];
            ((float4*)zd)[0] = make_float4(z.x, z.x, z.y, z.y);
            ((float4*)zd)[1] = make_float4(z.z, z.z, z.w, z.w);
        }
    }
    __syncthreads();

    {
        int oc = tid & 15, cg = tid >> 4;
        int ob = oc * 4;
        unsigned long long a01[4] = {0ull, 0ull, 0ull, 0ull};
        unsigned long long a23[4] = {0ull, 0ull, 0ull, 0ull};
        const float* z0 = &z0sD[(cg * 4 + 0) * Z0STRIDE];
        const float* z1 = &z0sD[(cg * 4 + 1) * Z0STRIDE];
        const float* z2 = &z0sD[(cg * 4 + 2) * Z0STRIDE];
        const float* z3 = &z0sD[(cg * 4 + 3) * Z0STRIDE];
#pragma unroll 8
        for (int k = 0; k < 64; k++) {
            ulonglong2 wp = *(const ulonglong2*)&w1s[k * 64 + ob];
            unsigned long long q0 = *(const unsigned long long*)(z0 + 2 * k);
            unsigned long long q1 = *(const unsigned long long*)(z1 + 2 * k);
            unsigned long long q2 = *(const unsigned long long*)(z2 + 2 * k);
            unsigned long long q3 = *(const unsigned long long*)(z3 + 2 * k);
            FMA2(a01[0], q0, wp.x); FMA2(a23[0], q0, wp.y);
            FMA2(a01[1], q1, wp.x); FMA2(a23[1], q1, wp.y);
            FMA2(a01[2], q2, wp.x); FMA2(a23[2], q2, wp.y);
            FMA2(a01[3], q3, wp.x); FMA2(a23[3], q3, wp.y);
        }
        float4 bb = *(const float4*)&b1s[ob];
        float4 w2v = *(const float4*)&w2s[ob];
        float part[4];
#pragma unroll
        for (int q = 0; q < 4; q++) {
            float t0, t1, t2, t3;
            UNPACK2(t0, t1, a01[q]);
            UNPACK2(t2, t3, a23[q]);
            t0 += bb.x; t0 = t0 >= 0.f ? t0 : NEG * t0;
            t1 += bb.y; t1 = t1 >= 0.f ? t1 : NEG * t1;
            t2 += bb.z; t2 = t2 >= 0.f ? t2 : NEG * t2;
            t3 += bb.w; t3 = t3 >= 0.f ? t3 : NEG * t3;
            part[q] = t0 * w2v.x + t1 * w2v.y + t2 * w2v.z + t3 * w2v.w;
        }
#pragma unroll
        for (int q = 0; q < 4; q++) {
#pragma unroll
            for (int o = 8; o; o >>= 1)
                part[q] += __shfl_xor_sync(0xffffffffu, part[q], o);
        }
        if (oc == 0) {
#pragma unroll
            for (int q = 0; q < 4; q++) {
                int gc = base + cg * 4 + q;
                if (gc < C) y[gc] = part[q] + b2s[0];
            }
        }
    }
}

// ---------------- softmax (2 kernels, deterministic) ----------------
__global__ void k_softA(const float* __restrict__ y, int C) {
    __shared__ float mm[256], ss[256];
    float m = -3.402823466e38f, s = 0.f;
    for (int i = blockIdx.x * 256 + threadIdx.x; i < C; i += gridDim.x * 256) {
        float v = y[i];
        if (v > m) { s = s * expf(m - v) + 1.0f; m = v; }
        else s += expf(v - m);
    }
    mm[threadIdx.x] = m; ss[threadIdx.x] = s;
    __syncthreads();
    for (int st = 128; st; st >>= 1) {
        if (threadIdx.x < st) {
            float m2 = mm[threadIdx.x + st], s2 = ss[threadIdx.x + st];
            float M = fmaxf(mm[threadIdx.x], m2);
            ss[threadIdx.x] = ss[threadIdx.x] * expf(mm[threadIdx.x] - M) + s2 * expf(m2 - M);
            mm[threadIdx.x] = M;
        }
        __syncthreads();
    }
    if (threadIdx.x == 0) { g_part[blockIdx.x] = mm[0]; g_part[128 + blockIdx.x] = ss[0]; }
}

__global__ void k_softFin(const float* __restrict__ y, float* __restrict__ out, int C) {
    __shared__ float mm[128], ss[128];
    int t = threadIdx.x;
    if (t < 128) { mm[t] = g_part[t]; ss[t] = g_part[128 + t]; }
    __syncthreads();
    for (int st = 64; st; st >>= 1) {
        if (t < st) {
            float m2 = mm[t + st], s2 = ss[t + st];
            float M = fmaxf(mm[t], m2);
            ss[t] = ss[t] * expf(mm[t] - M) + s2 * expf(m2 - M);
            mm[t] = M;
        }
        __syncthreads();
    }
    float mx = mm[0];
    float inv = 1.0f / ss[0];
    for (int i = blockIdx.x * 256 + t; i < C; i += gridDim.x * 256)
        out[i] = expf(y[i] - mx) * inv;
}

// ---------------- host launcher ----------------
extern "C" void kernel_launch(void* const* d_in, const int* in_sizes, int n_in,
                              void* d_out, int out_size) {
    const float* x   = (const float*)d_in[0];
    const int* src   = (const int*)d_in[1];
    const int* dst   = (const int*)d_in[2];
    const int* cu    = (const int*)d_in[3];
    const int* cv    = (const int*)d_in[4];
    const float* cf  = (const float*)d_in[5];
    const float* ws0 = (const float*)d_in[6];
    const float* wn0 = (const float*)d_in[7];
    const float* b0  = (const float*)d_in[8];
    const float* ga0 = (const float*)d_in[9];
    const float* be0 = (const float*)d_in[10];
    const float* rm0 = (const float*)d_in[11];
    const float* rv0 = (const float*)d_in[12];
    const float* ws1 = (const float*)d_in[13];
    const float* wn1 = (const float*)d_in[14];
    const float* b1  = (const float*)d_in[15];
    const float* ga1 = (const float*)d_in[16];
    const float* be1 = (const float*)d_in[17];
    const float* rm1 = (const float*)d_in[18];
    const float* rv1 = (const float*)d_in[19];
    const float* mw0 = (const float*)d_in[20];
    const float* mb0 = (const float*)d_in[21];
    const float* mw1 = (const float*)d_in[22];
    const float* mb1 = (const float*)d_in[23];
    const float* mw2 = (const float*)d_in[24];
    const float* mb2 = (const float*)d_in[25];

    int E = in_sizes[1];
    int C = in_sizes[3];
    float* y = (float*)d_out;
    float* soft = y + C;

    float *h0p, *h1p, *pup, *pvp;
    cudaGetSymbolAddress((void**)&h0p, g_h0);
    cudaGetSymbolAddress((void**)&h1p, g_h1);
    cudaGetSymbolAddress((void**)&pup, g_pu);
    cudaGetSymbolAddress((void**)&pvp, g_pv);

    cudaFuncSetAttribute(k_fused, cudaFuncAttributeMaxDynamicSharedMemorySize, 196608);
    cudaFuncSetAttribute(k_prep, cudaFuncAttributeMaxDynamicSharedMemorySize, 131072);
    cudaFuncSetAttribute(k_cand, cudaFuncAttributeMaxDynamicSharedMemorySize, CAND_SMEM_FLOATS * 4);

    // 1: zero state
    k_zero<<<(Nn + 255) / 256, 256>>>();
    // 2: degree count
    k_count<<<1024, 256>>>(dst, E);
    // 3: scan + fill (single pass)
    k_scanfill<<<NB_SCAN, 1024>>>(src, dst, E);
    // 4: layer 0 (profiled position)
    k_fused<<<(Nn + 63) / 64, 512, 196608>>>(x, ws0, wn0, b0, ga0, be0, rm0, rv0, h0p, 0);
    // 5: layer 1 (+ nan_to_num)
    k_fused<<<(Nn + 63) / 64, 512, 196608>>>(h0p, ws1, wn1, b1, ga1, be1, rm1, rv1, h1p, 1);
    // 6: MLP layer0 hoisted to node level
    k_prep<<<(Nn + 63) / 64, 512, 131072>>>(h1p, mw0, pup, pvp);
    // 7: candidate tail -> y
    k_cand<<<(C + 63) / 64, 256, CAND_SMEM_FLOATS * 4>>>(pup, pvp, cu, cv, cf, mw0, mb0, mw1, mb1, mw2, mb2, y, C);
    // 8,9: softmax
    k_softA<<<128, 256>>>(y, C);
    k_softFin<<<256, 256>>>(y, soft, C);
}

// round 10
// speedup vs baseline: 1.4194x; 1.0153x over previous
#include <cuda_runtime.h>
#include <math.h>

#define Nn 50000
#define Ee 800000
#define Cc 100000
#define D 128
#define NEG 0.01f
#define BN_EPS 1e-5f
#define NB_SCAN 49

#define FMA2(d, a, b) asm("fma.rn.f32x2 %0, %1, %2, %0;" : "+l"(d) : "l"(a), "l"(b))
#define UNPACK2(lo, hi, v) asm("mov.b64 {%0, %1}, %2;" : "=f"(lo), "=f"(hi) : "l"(v))

// ---------------- scratch (static __device__, no allocation) ----------------
__device__ float g_h0[(size_t)Nn * D];
__device__ float g_h1[(size_t)Nn * D];
__device__ float g_pu[(size_t)Nn * 64];
__device__ float g_pv[(size_t)Nn * 64];
__device__ int   g_deg[Nn];
__device__ int   g_off[Nn + 1];
__device__ int   g_cur[Nn];
__device__ int   g_csr[Ee];
__device__ unsigned long long g_lb[NB_SCAN];  // lookback: (aggregate<<1)|1
__device__ unsigned int g_done;
__device__ float g_part[256];

// ---------------- zero state ----------------
__global__ void k_zero() {
    int i = blockIdx.x * blockDim.x + threadIdx.x;
    if (i < Nn) g_deg[i] = 0;
    if (i < NB_SCAN) g_lb[i] = 0ull;
    if (i == 0) g_done = 0u;
}

__global__ void k_count(const int* __restrict__ dst, int E) {
    for (int e = blockIdx.x * blockDim.x + threadIdx.x; e < E; e += gridDim.x * blockDim.x)
        atomicAdd(&g_deg[dst[e]], 1);
}

// ---------------- single-pass: scan (lookback) + grid barrier + CSR fill ----------------
__global__ void k_scanfill(const int* __restrict__ src, const int* __restrict__ dst, int E) {
    __shared__ int ws[32];
    __shared__ int preds[64];
    __shared__ int sbase;
    int b = blockIdx.x;
    int tid = threadIdx.x;
    int i = b * 1024 + tid;
    int lane = tid & 31, wid = tid >> 5;
    int v = (i < Nn) ? g_deg[i] : 0;
    int s = v;
#pragma unroll
    for (int o = 1; o < 32; o <<= 1) {
        int t = __shfl_up_sync(0xffffffffu, s, o);
        if (lane >= o) s += t;
    }
    if (lane == 31) ws[wid] = s;
    __syncthreads();
    if (wid == 0) {
        int t = ws[lane];
#pragma unroll
        for (int o = 1; o < 32; o <<= 1) {
            int u = __shfl_up_sync(0xffffffffu, t, o);
            if (lane >= o) t += u;
        }
        ws[lane] = t;
    }
    __syncthreads();
    s += wid ? ws[wid - 1] : 0;  // local inclusive

    if (tid == 1023)
        atomicExch(&g_lb[b], (((unsigned long long)(unsigned)s) << 1) | 1ull);

    if (tid < b) {
        unsigned long long x;
        do { x = atomicAdd(&g_lb[tid], 0ull); } while (!(x & 1ull));
        preds[tid] = (int)(x >> 1);
    }
    __syncthreads();
    if (tid == 0) {
        int acc = 0;
        for (int j = 0; j < b; j++) acc += preds[j];
        sbase = acc;
    }
    __syncthreads();
    s += sbase;

    if (i < Nn) {
        g_off[i + 1] = s;
        g_cur[i] = s - v;
    }
    if (i == 0) g_off[0] = 0;

    __threadfence();
    __syncthreads();
    if (tid == 0) {
        atomicAdd(&g_done, 1u);
        while (atomicAdd(&g_done, 0u) < (unsigned)gridDim.x) {}
    }
    __syncthreads();

    int stride = gridDim.x * 1024;
    for (int e = b * 1024 + tid; e < E; e += stride) {
        int d = dst[e];
        int p = atomicAdd(&g_cur[d], 1);
        g_csr[p] = src[e];
    }
}

// ---------------- fused: segment-mean agg + dual GEMM + BN + leaky ----------------
// 64 nodes/block, 512 threads (16 warps x 4 nodes). f32x2 k-pair packed FMAs.
// smem: sWsP[16384] (k-pair interleaved), sWnP[16384], sVal[64 x (x[128],a[128])] -> 192KB
__global__ void k_fused(const float* __restrict__ A,
                        const float* __restrict__ Ws, const float* __restrict__ Wn,
                        const float* __restrict__ bias, const float* __restrict__ gamma,
                        const float* __restrict__ beta, const float* __restrict__ rm,
                        const float* __restrict__ rv, float* __restrict__ out, int fixnan) {
    extern __shared__ float sm[];
    float* sWsP = sm;               // [0, 16384)   entry (kp*128+col)*2: (W[2kp][col], W[2kp+1][col])
    float* sWnP = sm + 16384;       // [16384, 32768)
    float* sVal = sm + 32768;       // [32768, 49152)  node stride 256: x[128] then a[128]
    // stage weights interleaved by k-pair
    for (int idx = threadIdx.x; idx < 4096; idx += 512) {
        int kp = idx >> 6;          // 0..63
        int cg = idx & 63;          // col pair: cols 2cg, 2cg+1
        float2 a0 = *(const float2*)&Ws[(2 * kp) * 128 + 2 * cg];
        float2 b0 = *(const float2*)&Ws[(2 * kp + 1) * 128 + 2 * cg];
        *(float4*)&sWsP[(kp * 128 + 2 * cg) * 2] = make_float4(a0.x, b0.x, a0.y, b0.y);
        float2 a1 = *(const float2*)&Wn[(2 * kp) * 128 + 2 * cg];
        float2 b1 = *(const float2*)&Wn[(2 * kp + 1) * 128 + 2 * cg];
        *(float4*)&sWnP[(kp * 128 + 2 * cg) * 2] = make_float4(a1.x, b1.x, a1.y, b1.y);
    }
    __syncthreads();

    int w = threadIdx.x >> 5, l = threadIdx.x & 31;
    int nl0 = w * 4;
    int n0 = blockIdx.x * 64 + nl0;

    // ---------------- phase A: gather-mean, cross-node interleaved ----------------
    float4 xv[4], ag[4];
    int st[4], dg[4], ct[4], idx[4];
#pragma unroll
    for (int t = 0; t < 4; t++) {
        int node = n0 + t;
        xv[t] = make_float4(0.f, 0.f, 0.f, 0.f);
        ag[t] = make_float4(0.f, 0.f, 0.f, 0.f);
        st[t] = 0; dg[t] = 0;
        if (node < Nn) {
            st[t] = g_off[node];
            dg[t] = g_off[node + 1] - st[t];
            xv[t] = ((const float4*)(A + (size_t)node * D))[l];
        }
    }
#pragma unroll
    for (int t = 0; t < 4; t++) {
        ct[t] = dg[t] < 32 ? dg[t] : 32;
        idx[t] = (l < ct[t]) ? g_csr[st[t] + l] : 0;
    }
    // interleaved first chunk: up to 16 independent row loads in flight
    for (int j = 0; j < 32; j += 4) {
#pragma unroll
        for (int t = 0; t < 4; t++) {
            if (j + 4 <= ct[t]) {
                int r0 = __shfl_sync(0xffffffffu, idx[t], j);
                int r1 = __shfl_sync(0xffffffffu, idx[t], j + 1);
                int r2 = __shfl_sync(0xffffffffu, idx[t], j + 2);
                int r3 = __shfl_sync(0xffffffffu, idx[t], j + 3);
                float4 v0 = ((const float4*)(A + (size_t)r0 * D))[l];
                float4 v1 = ((const float4*)(A + (size_t)r1 * D))[l];
                float4 v2 = ((const float4*)(A + (size_t)r2 * D))[l];
                float4 v3 = ((const float4*)(A + (size_t)r3 * D))[l];
                ag[t].x += (v0.x + v1.x) + (v2.x + v3.x);
                ag[t].y += (v0.y + v1.y) + (v2.y + v3.y);
                ag[t].z += (v0.z + v1.z) + (v2.z + v3.z);
                ag[t].w += (v0.w + v1.w) + (v2.w + v3.w);
            }
        }
    }
    // remainders + extra chunks (rare: deg>32)
#pragma unroll
    for (int t = 0; t < 4; t++) {
        int node = n0 + t;
        if (node >= Nn) continue;
        for (int j = ct[t] & ~3; j < ct[t]; j++) {
            int r = __shfl_sync(0xffffffffu, idx[t], j);
            float4 vv = ((const float4*)(A + (size_t)r * D))[l];
            ag[t].x += vv.x; ag[t].y += vv.y; ag[t].z += vv.z; ag[t].w += vv.w;
        }
        for (int base = st[t] + 32; base < st[t] + dg[t]; base += 32) {
            int cnt = st[t] + dg[t] - base; if (cnt > 32) cnt = 32;
            int id2 = (l < cnt) ? g_csr[base + l] : 0;
            int j = 0;
            for (; j + 4 <= cnt; j += 4) {
                int r0 = __shfl_sync(0xffffffffu, id2, j);
                int r1 = __shfl_sync(0xffffffffu, id2, j + 1);
                int r2 = __shfl_sync(0xffffffffu, id2, j + 2);
                int r3 = __shfl_sync(0xffffffffu, id2, j + 3);
                float4 v0 = ((const float4*)(A + (size_t)r0 * D))[l];
                float4 v1 = ((const float4*)(A + (size_t)r1 * D))[l];
                float4 v2 = ((const float4*)(A + (size_t)r2 * D))[l];
                float4 v3 = ((const float4*)(A + (size_t)r3 * D))[l];
                ag[t].x += (v0.x + v1.x) + (v2.x + v3.x);
                ag[t].y += (v0.y + v1.y) + (v2.y + v3.y);
                ag[t].z += (v0.z + v1.z) + (v2.z + v3.z);
                ag[t].w += (v0.w + v1.w) + (v2.w + v3.w);
            }
            for (; j < cnt; j++) {
                int r = __shfl_sync(0xffffffffu, id2, j);
                float4 vv = ((const float4*)(A + (size_t)r * D))[l];
                ag[t].x += vv.x; ag[t].y += vv.y; ag[t].z += vv.z; ag[t].w += vv.w;
            }
        }
        float inv = 1.0f / (float)(dg[t] > 1 ? dg[t] : 1);
        ag[t].x *= inv; ag[t].y *= inv; ag[t].z *= inv; ag[t].w *= inv;
        *(float4*)(sVal + (nl0 + t) * 256 + l * 4) = xv[t];
        *(float4*)(sVal + (nl0 + t) * 256 + 128 + l * 4) = ag[t];
    }
    __syncwarp();

    // ---------------- phase B: k-pair packed f32x2; thread: 4 nodes x cols {2l,2l+1,64+2l,65+2l}
    const float* wsb = sWsP + 4 * l;
    const float* wnb = sWnP + 4 * l;
    const float* vb = sVal + nl0 * 256;
    unsigned long long acc[4][4];
#pragma unroll
    for (int t = 0; t < 4; t++)
#pragma unroll
        for (int j = 0; j < 4; j++) acc[t][j] = 0ull;
#pragma unroll 4
    for (int kp = 0; kp < 64; kp++) {
        ulonglong2 wA = *(const ulonglong2*)(wsb + kp * 256);        // cols 2l, 2l+1
        ulonglong2 wB = *(const ulonglong2*)(wsb + kp * 256 + 128);  // cols 64+2l, 65+2l
        ulonglong2 nA = *(const ulonglong2*)(wnb + kp * 256);
        ulonglong2 nB = *(const ulonglong2*)(wnb + kp * 256 + 128);
#pragma unroll
        for (int t = 0; t < 4; t++) {
            unsigned long long xx = *(const unsigned long long*)(vb + t * 256 + 2 * kp);
            unsigned long long aa = *(const unsigned long long*)(vb + t * 256 + 128 + 2 * kp);
            FMA2(acc[t][0], xx, wA.x); FMA2(acc[t][1], xx, wA.y);
            FMA2(acc[t][2], xx, wB.x); FMA2(acc[t][3], xx, wB.y);
            FMA2(acc[t][0], aa, nA.x); FMA2(acc[t][1], aa, nA.y);
            FMA2(acc[t][2], aa, nB.x); FMA2(acc[t][3], aa, nB.y);
        }
    }

    // epilogue: cols c0=2l, c1=2l+1, c2=64+2l, c3=65+2l
    int cA = 2 * l, cB = 64 + 2 * l;
    float2 bb01 = *(const float2*)&bias[cA];
    float2 bb23 = *(const float2*)&bias[cB];
    float2 ga01 = *(const float2*)&gamma[cA];
    float2 ga23 = *(const float2*)&gamma[cB];
    float2 be01 = *(const float2*)&beta[cA];
    float2 be23 = *(const float2*)&beta[cB];
    float2 rm01 = *(const float2*)&rm[cA];
    float2 rm23 = *(const float2*)&rm[cB];
    float2 rv01 = *(const float2*)&rv[cA];
    float2 rv23 = *(const float2*)&rv[cB];
    float scl[4], shf[4], bbv[4];
    scl[0] = ga01.x * rsqrtf(rv01.x + BN_EPS); shf[0] = be01.x - rm01.x * scl[0]; bbv[0] = bb01.x;
    scl[1] = ga01.y * rsqrtf(rv01.y + BN_EPS); shf[1] = be01.y - rm01.y * scl[1]; bbv[1] = bb01.y;
    scl[2] = ga23.x * rsqrtf(rv23.x + BN_EPS); shf[2] = be23.x - rm23.x * scl[2]; bbv[2] = bb23.x;
    scl[3] = ga23.y * rsqrtf(rv23.y + BN_EPS); shf[3] = be23.y - rm23.y * scl[3]; bbv[3] = bb23.y;
#pragma unroll
    for (int t = 0; t < 4; t++) {
        int node = n0 + t;
        if (node >= Nn) continue;
        float o[4];
#pragma unroll
        for (int j = 0; j < 4; j++) {
            float pe, po;
            UNPACK2(pe, po, acc[t][j]);
            float vv = (pe + po) + bbv[j];
            vv = vv * scl[j] + shf[j];
            vv = vv >= 0.f ? vv : NEG * vv;
            if (fixnan) {
                if (isnan(vv)) vv = 1e-14f;
                else if (isinf(vv)) vv = vv > 0.f ? 3.402823466e38f : -3.402823466e38f;
            }
            o[j] = vv;
        }
        *(float2*)&out[(size_t)node * D + cA] = make_float2(o[0], o[1]);
        *(float2*)&out[(size_t)node * D + cB] = make_float2(o[2], o[3]);
    }
}

// ---------------- node-level MLP layer0 projection (f32x2) ----------------
// 64 nodes/block, 512 threads (16 warps x 4 nodes); lane l -> cols (2l, 2l+1).
__global__ void k_prep(const float* __restrict__ h, const float* __restrict__ mw0,
                       float* __restrict__ pu, float* __restrict__ pv) {
    extern __shared__ float sm[];
    float* sWI = sm;            // [0, 16384)
    float* sVal = sm + 16384;   // [16384, 32768)  node stride 256
    for (int idx = threadIdx.x; idx < 4096; idx += 512) {
        int k = idx >> 5, p = idx & 31;
        float2 u = *(const float2*)&mw0[k * 64 + 2 * p];
        float2 v = *(const float2*)&mw0[(128 + k) * 64 + 2 * p];
        *(float4*)&sWI[k * 128 + p * 4] = make_float4(u.x, u.y, v.x, v.y);
    }
    __syncthreads();

    int w = threadIdx.x >> 5, l = threadIdx.x & 31;
    int nl0 = w * 4;
    int n0 = blockIdx.x * 64 + nl0;

#pragma unroll
    for (int t = 0; t < 4; t++) {
        int node = n0 + t;
        float4 xv = make_float4(0.f, 0.f, 0.f, 0.f);
        if (node < Nn) xv = ((const float4*)(h + (size_t)node * D))[l];
        float4* sd = (float4*)(sVal + (nl0 + t) * 256 + l * 8);
        sd[0] = make_float4(xv.x, xv.x, xv.y, xv.y);
        sd[1] = make_float4(xv.z, xv.z, xv.w, xv.w);
    }
    __syncwarp();

    unsigned long long au[4] = {0ull, 0ull, 0ull, 0ull};
    unsigned long long av[4] = {0ull, 0ull, 0ull, 0ull};
    const float* wib = sWI + l * 4;
    const float* vb = sVal + nl0 * 256;
#pragma unroll 8
    for (int k = 0; k < 128; k++) {
        ulonglong2 wp = *(const ulonglong2*)(wib + k * 128);  // (wu pair, wv pair)
#pragma unroll
        for (int t = 0; t < 4; t++) {
            unsigned long long xd = *(const unsigned long long*)(vb + t * 256 + 2 * k);
            FMA2(au[t], xd, wp.x);
            FMA2(av[t], xd, wp.y);
        }
    }
#pragma unroll
    for (int t = 0; t < 4; t++) {
        int node = n0 + t;
        if (node >= Nn) continue;
        *(float2*)&pu[(size_t)node * 64 + 2 * l] = *(float2*)&au[t];
        *(float2*)&pv[(size_t)node * 64 + 2 * l] = *(float2*)&av[t];
    }
}

// ---------------- candidate kernel ----------------
#define Z0STRIDE 136
#define CAND_SMEM_FLOATS 13060
__global__ void k_cand(const float* __restrict__ pu, const float* __restrict__ pv,
                       const int* __restrict__ cu, const int* __restrict__ cv,
                       const float* __restrict__ cf,
                       const float* __restrict__ mw0, const float* __restrict__ mb0,
                       const float* __restrict__ mw1, const float* __restrict__ mb1,
                       const float* __restrict__ mw2, const float* __restrict__ mb2,
                       float* __restrict__ y, int C) {
    extern __shared__ float smc[];
    float* w1s = smc;
    float* z0sD = smc + 4096;
    float* wfs = smc + 12800;
    float* b0s = smc + 12864;
    float* b1s = smc + 12928;
    float* w2s = smc + 12992;
    float* b2s = smc + 13056;
    int tid = threadIdx.x;
    for (int i = tid; i < 4096; i += 256) w1s[i] = mw1[i];
    if (tid < 64) {
        wfs[tid] = mw0[256 * 64 + tid];
        b0s[tid] = mb0[tid];
        b1s[tid] = mb1[tid];
        w2s[tid] = mw2[tid];
    }
    if (tid == 0) b2s[0] = mb2[0];
    __syncthreads();

    int base = blockIdx.x * 64;

    {
        int jc = tid & 15, j = jc * 4;
        int c0 = tid >> 4;
#pragma unroll
        for (int i = 0; i < 4; i++) {
            int cl = c0 + 16 * i;
            int gc = base + cl;
            float4 z = make_float4(0.f, 0.f, 0.f, 0.f);
            if (gc < C) {
                int u = cu[gc], v = cv[gc];
                float f = cf[gc];
                float4 a = *(const float4*)&pu[(size_t)u * 64 + j];
                float4 b = *(const float4*)&pv[(size_t)v * 64 + j];
                float4 wf4 = *(const float4*)&wfs[j];
                float4 bb4 = *(const float4*)&b0s[j];
                z.x = a.x + b.x + f * wf4.x + bb4.x;
                z.y = a.y + b.y + f * wf4.y + bb4.y;
                z.z = a.z + b.z + f * wf4.z + bb4.z;
                z.w = a.w + b.w + f * wf4.w + bb4.w;
                z.x = z.x >= 0.f ? z.x : NEG * z.x;
                z.y = z.y >= 0.f ? z.y : NEG * z.y;
                z.z = z.z >= 0.f ? z.z : NEG * z.z;
                z.w = z.w >= 0.f ? z.w : NEG * z.w;
            }
            float* zd = &z0sD[cl * Z0STRIDE + 2 * j];
            ((float4*)zd)[0] = make_float4(z.x, z.x, z.y, z.y);
            ((float4*)zd)[1] = make_float4(z.z, z.z, z.w, z.w);
        }
    }
    __syncthreads();

    {
        int oc = tid & 15, cg = tid >> 4;
        int ob = oc * 4;
        unsigned long long a01[4] = {0ull, 0ull, 0ull, 0ull};
        unsigned long long a23[4] = {0ull, 0ull, 0ull, 0ull};
        const float* z0 = &z0sD[(cg * 4 + 0) * Z0STRIDE];
        const float* z1 = &z0sD[(cg * 4 + 1) * Z0STRIDE];
        const float* z2 = &z0sD[(cg * 4 + 2) * Z0STRIDE];
        const float* z3 = &z0sD[(cg * 4 + 3) * Z0STRIDE];
#pragma unroll 8
        for (int k = 0; k < 64; k++) {
            ulonglong2 wp = *(const ulonglong2*)&w1s[k * 64 + ob];
            unsigned long long q0 = *(const unsigned long long*)(z0 + 2 * k);
            unsigned long long q1 = *(const unsigned long long*)(z1 + 2 * k);
            unsigned long long q2 = *(const unsigned long long*)(z2 + 2 * k);
            unsigned long long q3 = *(const unsigned long long*)(z3 + 2 * k);
            FMA2(a01[0], q0, wp.x); FMA2(a23[0], q0, wp.y);
            FMA2(a01[1], q1, wp.x); FMA2(a23[1], q1, wp.y);
            FMA2(a01[2], q2, wp.x); FMA2(a23[2], q2, wp.y);
            FMA2(a01[3], q3, wp.x); FMA2(a23[3], q3, wp.y);
        }
        float4 bb = *(const float4*)&b1s[ob];
        float4 w2v = *(const float4*)&w2s[ob];
        float part[4];
#pragma unroll
        for (int q = 0; q < 4; q++) {
            float t0, t1, t2, t3;
            UNPACK2(t0, t1, a01[q]);
            UNPACK2(t2, t3, a23[q]);
            t0 += bb.x; t0 = t0 >= 0.f ? t0 : NEG * t0;
            t1 += bb.y; t1 = t1 >= 0.f ? t1 : NEG * t1;
            t2 += bb.z; t2 = t2 >= 0.f ? t2 : NEG * t2;
            t3 += bb.w; t3 = t3 >= 0.f ? t3 : NEG * t3;
            part[q] = t0 * w2v.x + t1 * w2v.y + t2 * w2v.z + t3 * w2v.w;
        }
#pragma unroll
        for (int q = 0; q < 4; q++) {
#pragma unroll
            for (int o = 8; o; o >>= 1)
                part[q] += __shfl_xor_sync(0xffffffffu, part[q], o);
        }
        if (oc == 0) {
#pragma unroll
            for (int q = 0; q < 4; q++) {
                int gc = base + cg * 4 + q;
                if (gc < C) y[gc] = part[q] + b2s[0];
            }
        }
    }
}

// ---------------- softmax (2 kernels, deterministic) ----------------
__global__ void k_softA(const float* __restrict__ y, int C) {
    __shared__ float mm[256], ss[256];
    float m = -3.402823466e38f, s = 0.f;
    for (int i = blockIdx.x * 256 + threadIdx.x; i < C; i += gridDim.x * 256) {
        float v = y[i];
        if (v > m) { s = s * expf(m - v) + 1.0f; m = v; }
        else s += expf(v - m);
    }
    mm[threadIdx.x] = m; ss[threadIdx.x] = s;
    __syncthreads();
    for (int st = 128; st; st >>= 1) {
        if (threadIdx.x < st) {
            float m2 = mm[threadIdx.x + st], s2 = ss[threadIdx.x + st];
            float M = fmaxf(mm[threadIdx.x], m2);
            ss[threadIdx.x] = ss[threadIdx.x] * expf(mm[threadIdx.x] - M) + s2 * expf(m2 - M);
            mm[threadIdx.x] = M;
        }
        __syncthreads();
    }
    if (threadIdx.x == 0) { g_part[blockIdx.x] = mm[0]; g_part[128 + blockIdx.x] = ss[0]; }
}

__global__ void k_softFin(const float* __restrict__ y, float* __restrict__ out, int C) {
    __shared__ float mm[128], ss[128];
    int t = threadIdx.x;
    if (t < 128) { mm[t] = g_part[t]; ss[t] = g_part[128 + t]; }
    __syncthreads();
    for (int st = 64; st; st >>= 1) {
        if (t < st) {
            float m2 = mm[t + st], s2 = ss[t + st];
            float M = fmaxf(mm[t], m2);
            ss[t] = ss[t] * expf(mm[t] - M) + s2 * expf(m2 - M);
            mm[t] = M;
        }
        __syncthreads();
    }
    float mx = mm[0];
    float inv = 1.0f / ss[0];
    for (int i = blockIdx.x * 256 + t; i < C; i += gridDim.x * 256)
        out[i] = expf(y[i] - mx) * inv;
}

// ---------------- host launcher ----------------
extern "C" void kernel_launch(void* const* d_in, const int* in_sizes, int n_in,
                              void* d_out, int out_size) {
    const float* x   = (const float*)d_in[0];
    const int* src   = (const int*)d_in[1];
    const int* dst   = (const int*)d_in[2];
    const int* cu    = (const int*)d_in[3];
    const int* cv    = (const int*)d_in[4];
    const float* cf  = (const float*)d_in[5];
    const float* ws0 = (const float*)d_in[6];
    const float* wn0 = (const float*)d_in[7];
    const float* b0  = (const float*)d_in[8];
    const float* ga0 = (const float*)d_in[9];
    const float* be0 = (const float*)d_in[10];
    const float* rm0 = (const float*)d_in[11];
    const float* rv0 = (const float*)d_in[12];
    const float* ws1 = (const float*)d_in[13];
    const float* wn1 = (const float*)d_in[14];
    const float* b1  = (const float*)d_in[15];
    const float* ga1 = (const float*)d_in[16];
    const float* be1 = (const float*)d_in[17];
    const float* rm1 = (const float*)d_in[18];
    const float* rv1 = (const float*)d_in[19];
    const float* mw0 = (const float*)d_in[20];
    const float* mb0 = (const float*)d_in[21];
    const float* mw1 = (const float*)d_in[22];
    const float* mb1 = (const float*)d_in[23];
    const float* mw2 = (const float*)d_in[24];
    const float* mb2 = (const float*)d_in[25];

    int E = in_sizes[1];
    int C = in_sizes[3];
    float* y = (float*)d_out;
    float* soft = y + C;

    float *h0p, *h1p, *pup, *pvp;
    cudaGetSymbolAddress((void**)&h0p, g_h0);
    cudaGetSymbolAddress((void**)&h1p, g_h1);
    cudaGetSymbolAddress((void**)&pup, g_pu);
    cudaGetSymbolAddress((void**)&pvp, g_pv);

    cudaFuncSetAttribute(k_fused, cudaFuncAttributeMaxDynamicSharedMemorySize, 196608);
    cudaFuncSetAttribute(k_prep, cudaFuncAttributeMaxDynamicSharedMemorySize, 131072);
    cudaFuncSetAttribute(k_cand, cudaFuncAttributeMaxDynamicSharedMemorySize, CAND_SMEM_FLOATS * 4);

    // 1: zero state
    k_zero<<<(Nn + 255) / 256, 256>>>();
    // 2: degree count
    k_count<<<1024, 256>>>(dst, E);
    // 3: scan + fill (single pass)
    k_scanfill<<<NB_SCAN, 1024>>>(src, dst, E);
    // 4: layer 0 (profiled position)
    k_fused<<<(Nn + 63) / 64, 512, 196608>>>(x, ws0, wn0, b0, ga0, be0, rm0, rv0, h0p, 0);
    // 5: layer 1 (+ nan_to_num)
    k_fused<<<(Nn + 63) / 64, 512, 196608>>>(h0p, ws1, wn1, b1, ga1, be1, rm1, rv1, h1p, 1);
    // 6: MLP layer0 hoisted to node level
    k_prep<<<(Nn + 63) / 64, 512, 131072>>>(h1p, mw0, pup, pvp);
    // 7: candidate tail -> y
    k_cand<<<(C + 63) / 64, 256, CAND_SMEM_FLOATS * 4>>>(pup, pvp, cu, cv, cf, mw0, mb0, mw1, mb1, mw2, mb2, y, C);
    // 8,9: softmax
    k_softA<<<128, 256>>>(y, C);
    k_softFin<<<256, 256>>>(y, soft, C);
}